// round 3
// baseline (speedup 1.0000x reference)
#include <cuda_runtime.h>
#include <math.h>

#define BB      2
#define SEQ     2048
#define DMODEL  1024
#define NHEAD   16
#define DHEAD   64
#define NTOK    (BB * SEQ)        // 4096
#define NBH     (BB * NHEAD)      // 32
#define ATTN_SCALE 0.125f         // 1/sqrt(64)

// ---------------------------------------------------------------------------
// Scratch (static __device__ globals -- allocation-free per harness rules)
// ---------------------------------------------------------------------------
__device__ float g_Q [(size_t)NTOK * DMODEL];
__device__ float g_K [(size_t)NTOK * DMODEL];
__device__ float g_V [(size_t)NTOK * DMODEL];
__device__ float g_X [(size_t)NTOK * DMODEL];
__device__ float g_SC[(size_t)NBH * SEQ * SEQ];   // raw scaled scores [bh][i][j]
__device__ float g_CM[NBH * SEQ];                 // per-column max over i
__device__ float g_CR[NBH * SEQ];                 // per-column 1/sum over i

// ---------------------------------------------------------------------------
// Generic NN GEMM with bias: C[M,N] = A[M,K] @ W[K,N] + bias[N]
// 128x128x8 tile, 256 threads, 8x8 micro-tile per thread.
// ---------------------------------------------------------------------------
__global__ __launch_bounds__(256) void gemm_nn_bias(
    const float* __restrict__ A, const float* __restrict__ W,
    const float* __restrict__ bias, float* __restrict__ C,
    int M, int N, int K)
{
    __shared__ __align__(16) float As[8][128];
    __shared__ __align__(16) float Bs[8][128];

    const int tid  = threadIdx.x;
    const int brow = blockIdx.y * 128;
    const int bcol = blockIdx.x * 128;

    // compute mapping: 8 warps in 4x2 grid, each warp 32x64; lanes 4x8, 8x8 tiles
    const int w = tid >> 5, l = tid & 31;
    const int trow = ((w >> 1) << 5) + ((l >> 3) << 3);   // 0..120 step 8
    const int tcol = ((w & 1) << 6) + ((l & 7) << 3);     // 0..120 step 8

    // load mapping
    const int ar = tid >> 1, ac = (tid & 1) * 4;          // A: 128 rows x 8 cols
    const int br = tid >> 5, bc = (tid & 31) * 4;         // W: 8 rows x 128 cols

    const float* Aptr = A + (size_t)(brow + ar) * K + ac;
    const float* Wptr = W + (size_t)br * N + bcol + bc;

    float acc[8][8];
#pragma unroll
    for (int i = 0; i < 8; i++)
#pragma unroll
        for (int j = 0; j < 8; j++) acc[i][j] = 0.f;

    for (int k0 = 0; k0 < K; k0 += 8) {
        float4 av = *(const float4*)(Aptr + k0);
        As[ac + 0][ar] = av.x; As[ac + 1][ar] = av.y;
        As[ac + 2][ar] = av.z; As[ac + 3][ar] = av.w;
        float4 wv = *(const float4*)(Wptr + (size_t)k0 * N);
        *(float4*)&Bs[br][bc] = wv;
        __syncthreads();
#pragma unroll
        for (int kk = 0; kk < 8; kk++) {
            float ra[8], rb[8];
            *(float4*)&ra[0] = *(const float4*)&As[kk][trow];
            *(float4*)&ra[4] = *(const float4*)&As[kk][trow + 4];
            *(float4*)&rb[0] = *(const float4*)&Bs[kk][tcol];
            *(float4*)&rb[4] = *(const float4*)&Bs[kk][tcol + 4];
#pragma unroll
            for (int i = 0; i < 8; i++)
#pragma unroll
                for (int j = 0; j < 8; j++)
                    acc[i][j] = fmaf(ra[i], rb[j], acc[i][j]);
        }
        __syncthreads();
    }

#pragma unroll
    for (int i = 0; i < 8; i++) {
        size_t roff = (size_t)(brow + trow + i) * N + bcol + tcol;
#pragma unroll
        for (int j = 0; j < 8; j += 4) {
            float4 o;
            o.x = acc[i][j + 0] + bias[bcol + tcol + j + 0];
            o.y = acc[i][j + 1] + bias[bcol + tcol + j + 1];
            o.z = acc[i][j + 2] + bias[bcol + tcol + j + 2];
            o.w = acc[i][j + 3] + bias[bcol + tcol + j + 3];
            *(float4*)&C[roff + j] = o;
        }
    }
}

// ---------------------------------------------------------------------------
// Scores: S[bh][i][j] = scale * sum_d Q[b,i,h,d] * K[b,j,h,d]   (NT, strided)
// 128x128x16 tile per block; grid (S/128 j-tiles, S/128 i-tiles, BH)
// ---------------------------------------------------------------------------
__global__ __launch_bounds__(256) void qk_scores()
{
    __shared__ __align__(16) float As[16][128];
    __shared__ __align__(16) float Bs[16][128];

    const int tid = threadIdx.x;
    const int bh  = blockIdx.z;
    const int b   = bh / NHEAD, h = bh % NHEAD;
    const int browi = blockIdx.y * 128;   // i tile
    const int bcolj = blockIdx.x * 128;   // j tile

    const float* Ab = g_Q + ((size_t)b * SEQ * DMODEL) + (size_t)h * DHEAD;
    const float* Bb = g_K + ((size_t)b * SEQ * DMODEL) + (size_t)h * DHEAD;
    float*       Cb = g_SC + (size_t)bh * SEQ * SEQ;

    const int w = tid >> 5, l = tid & 31;
    const int trow = ((w >> 1) << 5) + ((l >> 3) << 3);
    const int tcol = ((w & 1) << 6) + ((l & 7) << 3);

    float acc[8][8];
#pragma unroll
    for (int i = 0; i < 8; i++)
#pragma unroll
        for (int j = 0; j < 8; j++) acc[i][j] = 0.f;

    for (int k0 = 0; k0 < DHEAD; k0 += 16) {
#pragma unroll
        for (int it = 0; it < 2; it++) {
            int f   = tid + it * 256;         // 512 float4 per tile
            int row = f >> 2;
            int c4  = (f & 3) * 4;
            float4 qa = *(const float4*)(Ab + (size_t)(browi + row) * DMODEL + k0 + c4);
            As[c4 + 0][row] = qa.x; As[c4 + 1][row] = qa.y;
            As[c4 + 2][row] = qa.z; As[c4 + 3][row] = qa.w;
            float4 kb = *(const float4*)(Bb + (size_t)(bcolj + row) * DMODEL + k0 + c4);
            Bs[c4 + 0][row] = kb.x; Bs[c4 + 1][row] = kb.y;
            Bs[c4 + 2][row] = kb.z; Bs[c4 + 3][row] = kb.w;
        }
        __syncthreads();
#pragma unroll
        for (int kk = 0; kk < 16; kk++) {
            float ra[8], rb[8];
            *(float4*)&ra[0] = *(const float4*)&As[kk][trow];
            *(float4*)&ra[4] = *(const float4*)&As[kk][trow + 4];
            *(float4*)&rb[0] = *(const float4*)&Bs[kk][tcol];
            *(float4*)&rb[4] = *(const float4*)&Bs[kk][tcol + 4];
#pragma unroll
            for (int i = 0; i < 8; i++)
#pragma unroll
                for (int j = 0; j < 8; j++)
                    acc[i][j] = fmaf(ra[i], rb[j], acc[i][j]);
        }
        __syncthreads();
    }

#pragma unroll
    for (int i = 0; i < 8; i++) {
        size_t roff = (size_t)(browi + trow + i) * SEQ + bcolj + tcol;
#pragma unroll
        for (int j = 0; j < 8; j += 4) {
            float4 o;
            o.x = acc[i][j + 0] * ATTN_SCALE;
            o.y = acc[i][j + 1] * ATTN_SCALE;
            o.z = acc[i][j + 2] * ATTN_SCALE;
            o.w = acc[i][j + 3] * ATTN_SCALE;
            *(float4*)&Cb[roff + j] = o;
        }
    }
}

// ---------------------------------------------------------------------------
// Column stats over i (softmax over axis=1): per (bh, j): max and 1/sum.
// Coalesced: threads = consecutive j; loop over i (8-way batched for MLP).
// ---------------------------------------------------------------------------
__global__ __launch_bounds__(256) void col_stats()
{
    const int bh = blockIdx.y;
    const int j  = blockIdx.x * 256 + threadIdx.x;
    const float* base = g_SC + (size_t)bh * SEQ * SEQ + j;

    float m = -1e30f, c = 0.f;
    for (int i = 0; i < SEQ; i += 8) {
        float s[8];
#pragma unroll
        for (int u = 0; u < 8; u++) s[u] = base[(size_t)(i + u) * SEQ];
        float mb = s[0];
#pragma unroll
        for (int u = 1; u < 8; u++) mb = fmaxf(mb, s[u]);
        float mn = fmaxf(m, mb);
        float cs = 0.f;
#pragma unroll
        for (int u = 0; u < 8; u++) cs += __expf(s[u] - mn);
        c = c * __expf(m - mn) + cs;
        m = mn;
    }
    g_CM[bh * SEQ + j] = m;
    g_CR[bh * SEQ + j] = 1.0f / c;
}

// ---------------------------------------------------------------------------
// AV GEMM with fused softmax normalization on the A(scores)-tile load:
//   X[b,i,h,d] = sum_j exp(S[i,j]-m_j)*rcp_j * V[b,j,h,d]
// Block: 128(i) x 64(d), BK=16, 256 threads, 4x8 micro-tiles.
// ---------------------------------------------------------------------------
__global__ __launch_bounds__(256) void av_gemm()
{
    __shared__ __align__(16) float As[16][128];
    __shared__ __align__(16) float Bs[16][64];

    const int tid = threadIdx.x;
    const int bh  = blockIdx.y;
    const int b   = bh / NHEAD, h = bh % NHEAD;
    const int browi = blockIdx.x * 128;

    const float* Sb = g_SC + (size_t)bh * SEQ * SEQ;
    const float* cm = g_CM + bh * SEQ;
    const float* cr = g_CR + bh * SEQ;
    const float* Vb = g_V + ((size_t)b * SEQ * DMODEL) + (size_t)h * DHEAD;

    // compute mapping: 8 warps in 4x2 grid (32x32 regions); lanes 8x4; 4x8 tiles
    const int w = tid >> 5, l = tid & 31;
    const int trow = ((w >> 1) << 5) + ((l >> 2) << 2);   // 0..124 step 4
    const int tcol = ((w & 1) << 5) + ((l & 3) << 3);     // 0..56  step 8

    // loaders
    const int c4 = (tid & 3) * 4;     // score column group (same for both halves)
    const int vr = tid >> 4, vc = (tid & 15) * 4;

    float acc[4][8];
#pragma unroll
    for (int i = 0; i < 4; i++)
#pragma unroll
        for (int j = 0; j < 8; j++) acc[i][j] = 0.f;

    for (int k0 = 0; k0 < SEQ; k0 += 16) {
        // per-thread column stats for this k-tile (4 columns, reused twice)
        const float m0 = cm[k0 + c4 + 0], r0 = cr[k0 + c4 + 0];
        const float m1 = cm[k0 + c4 + 1], r1 = cr[k0 + c4 + 1];
        const float m2 = cm[k0 + c4 + 2], r2 = cr[k0 + c4 + 2];
        const float m3 = cm[k0 + c4 + 3], r3 = cr[k0 + c4 + 3];
#pragma unroll
        for (int it = 0; it < 2; it++) {
            int row = (tid + it * 256) >> 2;
            float4 sv = *(const float4*)(Sb + (size_t)(browi + row) * SEQ + k0 + c4);
            As[c4 + 0][row] = __expf(sv.x - m0) * r0;
            As[c4 + 1][row] = __expf(sv.y - m1) * r1;
            As[c4 + 2][row] = __expf(sv.z - m2) * r2;
            As[c4 + 3][row] = __expf(sv.w - m3) * r3;
        }
        float4 vv = *(const float4*)(Vb + (size_t)(k0 + vr) * DMODEL + vc);
        *(float4*)&Bs[vr][vc] = vv;
        __syncthreads();
#pragma unroll
        for (int kk = 0; kk < 16; kk++) {
            float ra[4], rb[8];
            *(float4*)&ra[0] = *(const float4*)&As[kk][trow];
            *(float4*)&rb[0] = *(const float4*)&Bs[kk][tcol];
            *(float4*)&rb[4] = *(const float4*)&Bs[kk][tcol + 4];
#pragma unroll
            for (int i = 0; i < 4; i++)
#pragma unroll
                for (int j = 0; j < 8; j++)
                    acc[i][j] = fmaf(ra[i], rb[j], acc[i][j]);
        }
        __syncthreads();
    }

#pragma unroll
    for (int i = 0; i < 4; i++) {
        size_t tok = (size_t)b * SEQ + browi + trow + i;
        float* op = g_X + tok * DMODEL + h * DHEAD + tcol;
        float4 o0, o1;
        o0.x = acc[i][0]; o0.y = acc[i][1]; o0.z = acc[i][2]; o0.w = acc[i][3];
        o1.x = acc[i][4]; o1.y = acc[i][5]; o1.z = acc[i][6]; o1.w = acc[i][7];
        *(float4*)op       = o0;
        *(float4*)(op + 4) = o1;
    }
}

// ---------------------------------------------------------------------------
// Launch
// ---------------------------------------------------------------------------
extern "C" void kernel_launch(void* const* d_in, const int* in_sizes, int n_in,
                              void* d_out, int out_size)
{
    const float* query = (const float*)d_in[0];
    const float* key_  = (const float*)d_in[1];
    const float* value = (const float*)d_in[2];
    const float* Wq = (const float*)d_in[3];
    const float* bq = (const float*)d_in[4];
    const float* Wk = (const float*)d_in[5];
    const float* bk = (const float*)d_in[6];
    const float* Wv = (const float*)d_in[7];
    const float* bv = (const float*)d_in[8];
    const float* Wo = (const float*)d_in[9];
    const float* bo = (const float*)d_in[10];
    float* out = (float*)d_out;

    float *Qp, *Kp, *Vp, *Xp;
    cudaGetSymbolAddress((void**)&Qp, g_Q);
    cudaGetSymbolAddress((void**)&Kp, g_K);
    cudaGetSymbolAddress((void**)&Vp, g_V);
    cudaGetSymbolAddress((void**)&Xp, g_X);

    dim3 blk(256);
    dim3 gproj(DMODEL / 128, NTOK / 128);   // (8, 32)

    gemm_nn_bias<<<gproj, blk>>>(query, Wq, bq, Qp, NTOK, DMODEL, DMODEL);
    gemm_nn_bias<<<gproj, blk>>>(key_,  Wk, bk, Kp, NTOK, DMODEL, DMODEL);
    gemm_nn_bias<<<gproj, blk>>>(value, Wv, bv, Vp, NTOK, DMODEL, DMODEL);

    qk_scores<<<dim3(SEQ / 128, SEQ / 128, NBH), blk>>>();
    col_stats<<<dim3(SEQ / 256, NBH), blk>>>();
    av_gemm<<<dim3(SEQ / 128, NBH), blk>>>();

    gemm_nn_bias<<<gproj, blk>>>(Xp, Wo, bo, out, NTOK, DMODEL, DMODEL);
}

// round 4
// speedup vs baseline: 2.1210x; 2.1210x over previous
#include <cuda_runtime.h>
#include <math.h>

#define BB      2
#define SEQ     2048
#define DMODEL  1024
#define NHEAD   16
#define DHEAD   64
#define NTOK    (BB * SEQ)        // 4096
#define NBH     (BB * NHEAD)      // 32
#define ATTN_SCALE 0.125f         // 1/sqrt(64)

// ---------------------------------------------------------------------------
// Scratch
// ---------------------------------------------------------------------------
__device__ float g_Q [(size_t)NTOK * DMODEL];
__device__ float g_K [(size_t)NTOK * DMODEL];
__device__ float g_V [(size_t)NTOK * DMODEL];
__device__ float g_X [(size_t)NTOK * DMODEL];
__device__ float g_SC[(size_t)NBH * SEQ * SEQ];   // raw scaled scores [bh][i][j]
__device__ float g_CM[NBH * SEQ];                 // per-column max over i
__device__ float g_CR[NBH * SEQ];                 // per-column 1/sum over i

// ---------------------------------------------------------------------------
// Helpers: tf32 convert, mma.m16n8k8, cp.async
// ---------------------------------------------------------------------------
__device__ __forceinline__ unsigned f2tf(float x) {
    unsigned r;
    asm("cvt.rna.tf32.f32 %0, %1;" : "=r"(r) : "f"(x));
    return r;
}

__device__ __forceinline__ void mma_tf32(float* c, const unsigned* a, const unsigned* b) {
    asm volatile(
        "mma.sync.aligned.m16n8k8.row.col.f32.tf32.tf32.f32 "
        "{%0,%1,%2,%3}, {%4,%5,%6,%7}, {%8,%9}, {%0,%1,%2,%3};"
        : "+f"(c[0]), "+f"(c[1]), "+f"(c[2]), "+f"(c[3])
        : "r"(a[0]), "r"(a[1]), "r"(a[2]), "r"(a[3]), "r"(b[0]), "r"(b[1]));
}

__device__ __forceinline__ void cp16(void* smem, const void* g) {
    unsigned s = (unsigned)__cvta_generic_to_shared(smem);
    asm volatile("cp.async.cg.shared.global [%0], [%1], 16;" :: "r"(s), "l"(g));
}
#define CP_COMMIT asm volatile("cp.async.commit_group;")
#define CP_WAIT0  asm volatile("cp.async.wait_group 0;")

// ---------------------------------------------------------------------------
// Projection GEMM (tf32): C[M,N] = A[M,K] @ W[K,N] + bias
// 128x128 block, BK=16 double-buffered cp.async, 8 warps (2x4), warp 64x32.
// ---------------------------------------------------------------------------
__global__ __launch_bounds__(256) void gemm_nn_tf32(
    const float* __restrict__ A, const float* __restrict__ W,
    const float* __restrict__ bias, float* __restrict__ C,
    int M, int N, int K)
{
    __shared__ float As[2][128][20];   // [m][k], pad 20 -> frag banks 20g+t distinct
    __shared__ float Bs[2][16][136];   // [k][n], pad 136 -> frag banks 8t+g distinct

    const int tid  = threadIdx.x;
    const int brow = blockIdx.y * 128;
    const int bcol = blockIdx.x * 128;
    const int w = tid >> 5, lane = tid & 31;
    const int g = lane >> 2, t = lane & 3;
    const int warpM = (w >> 2) * 64;   // 0 / 64
    const int warpN = (w & 3) * 32;    // 0..96

    const int arow = tid >> 2, ac4 = (tid & 3) * 4;
    const int brw  = tid >> 5, bc4 = (tid & 31) * 4;

    float acc[4][4][4];
#pragma unroll
    for (int mt = 0; mt < 4; mt++)
#pragma unroll
        for (int nt = 0; nt < 4; nt++)
#pragma unroll
            for (int i = 0; i < 4; i++) acc[mt][nt][i] = 0.f;

    auto load_tiles = [&](int buf, int k0) {
        cp16(&As[buf][arow][ac4],      A + (size_t)(brow + arow) * K + k0 + ac4);
        cp16(&As[buf][arow + 64][ac4], A + (size_t)(brow + arow + 64) * K + k0 + ac4);
        cp16(&Bs[buf][brw][bc4],       W + (size_t)(k0 + brw) * N + bcol + bc4);
        cp16(&Bs[buf][brw + 8][bc4],   W + (size_t)(k0 + brw + 8) * N + bcol + bc4);
        CP_COMMIT;
    };

    load_tiles(0, 0);
    int buf = 0;
    for (int k0 = 0; k0 < K; k0 += 16) {
        CP_WAIT0;
        __syncthreads();
        if (k0 + 16 < K) load_tiles(buf ^ 1, k0 + 16);
#pragma unroll
        for (int ks = 0; ks < 2; ks++) {
            const int k = ks * 8;
            unsigned af[4][4], bf[4][2];
#pragma unroll
            for (int mt = 0; mt < 4; mt++) {
                int r = warpM + mt * 16 + g;
                af[mt][0] = f2tf(As[buf][r][k + t]);
                af[mt][1] = f2tf(As[buf][r + 8][k + t]);
                af[mt][2] = f2tf(As[buf][r][k + t + 4]);
                af[mt][3] = f2tf(As[buf][r + 8][k + t + 4]);
            }
#pragma unroll
            for (int nt = 0; nt < 4; nt++) {
                int c = warpN + nt * 8 + g;
                bf[nt][0] = f2tf(Bs[buf][k + t][c]);
                bf[nt][1] = f2tf(Bs[buf][k + t + 4][c]);
            }
#pragma unroll
            for (int mt = 0; mt < 4; mt++)
#pragma unroll
                for (int nt = 0; nt < 4; nt++)
                    mma_tf32(acc[mt][nt], af[mt], bf[nt]);
        }
        buf ^= 1;
        __syncthreads();
    }

#pragma unroll
    for (int mt = 0; mt < 4; mt++) {
        int r0 = brow + warpM + mt * 16 + g;
#pragma unroll
        for (int nt = 0; nt < 4; nt++) {
            int c = bcol + warpN + nt * 8 + 2 * t;
            float b0 = bias[c], b1 = bias[c + 1];
            float2 v0 = make_float2(acc[mt][nt][0] + b0, acc[mt][nt][1] + b1);
            float2 v1 = make_float2(acc[mt][nt][2] + b0, acc[mt][nt][3] + b1);
            *(float2*)&C[(size_t)r0 * N + c]       = v0;
            *(float2*)&C[(size_t)(r0 + 8) * N + c] = v1;
        }
    }
}

// ---------------------------------------------------------------------------
// QK^T scores (tf32, NT): S[bh][i][j] = scale * Q[b,i,h,:] . K[b,j,h,:]
// 128x128 block, K=64 in two 32-chunks, 8 warps (2x4).
// ---------------------------------------------------------------------------
__global__ __launch_bounds__(256) void qk_tf32()
{
    __shared__ float Qs[128][36];   // [i][k] pad 36 -> banks 4g+t distinct
    __shared__ float Ks[128][36];   // [j][k] same pattern

    const int tid = threadIdx.x;
    const int bh  = blockIdx.z, b = bh >> 4, h = bh & 15;
    const int browi = blockIdx.y * 128;
    const int bcolj = blockIdx.x * 128;

    const float* Qb = g_Q + (size_t)b * SEQ * DMODEL + (size_t)h * DHEAD;
    const float* Kb = g_K + (size_t)b * SEQ * DMODEL + (size_t)h * DHEAD;
    float*       Cb = g_SC + (size_t)bh * SEQ * SEQ;

    const int w = tid >> 5, lane = tid & 31;
    const int g = lane >> 2, t = lane & 3;
    const int warpM = (w >> 2) * 64, warpN = (w & 3) * 32;
    const int lc4 = (tid & 7) * 4;

    float acc[4][4][4];
#pragma unroll
    for (int mt = 0; mt < 4; mt++)
#pragma unroll
        for (int nt = 0; nt < 4; nt++)
#pragma unroll
            for (int i = 0; i < 4; i++) acc[mt][nt][i] = 0.f;

    for (int k0 = 0; k0 < DHEAD; k0 += 32) {
#pragma unroll
        for (int i = 0; i < 4; i++) {
            int row = (tid + i * 256) >> 3;
            cp16(&Qs[row][lc4], Qb + (size_t)(browi + row) * DMODEL + k0 + lc4);
            cp16(&Ks[row][lc4], Kb + (size_t)(bcolj + row) * DMODEL + k0 + lc4);
        }
        CP_COMMIT; CP_WAIT0;
        __syncthreads();
#pragma unroll
        for (int ks = 0; ks < 4; ks++) {
            const int k = ks * 8;
            unsigned af[4][4], bf[4][2];
#pragma unroll
            for (int mt = 0; mt < 4; mt++) {
                int r = warpM + mt * 16 + g;
                af[mt][0] = f2tf(Qs[r][k + t]);
                af[mt][1] = f2tf(Qs[r + 8][k + t]);
                af[mt][2] = f2tf(Qs[r][k + t + 4]);
                af[mt][3] = f2tf(Qs[r + 8][k + t + 4]);
            }
#pragma unroll
            for (int nt = 0; nt < 4; nt++) {
                int c = warpN + nt * 8 + g;
                bf[nt][0] = f2tf(Ks[c][k + t]);
                bf[nt][1] = f2tf(Ks[c][k + t + 4]);
            }
#pragma unroll
            for (int mt = 0; mt < 4; mt++)
#pragma unroll
                for (int nt = 0; nt < 4; nt++)
                    mma_tf32(acc[mt][nt], af[mt], bf[nt]);
        }
        __syncthreads();
    }

#pragma unroll
    for (int mt = 0; mt < 4; mt++) {
        int r0 = browi + warpM + mt * 16 + g;
#pragma unroll
        for (int nt = 0; nt < 4; nt++) {
            int c = bcolj + warpN + nt * 8 + 2 * t;
            float2 v0 = make_float2(acc[mt][nt][0] * ATTN_SCALE, acc[mt][nt][1] * ATTN_SCALE);
            float2 v1 = make_float2(acc[mt][nt][2] * ATTN_SCALE, acc[mt][nt][3] * ATTN_SCALE);
            *(float2*)&Cb[(size_t)r0 * SEQ + c]       = v0;
            *(float2*)&Cb[(size_t)(r0 + 8) * SEQ + c] = v1;
        }
    }
}

// ---------------------------------------------------------------------------
// Column stats over i (softmax axis=1): per (bh, j): max and 1/sum. fp32.
// ---------------------------------------------------------------------------
__global__ __launch_bounds__(256) void col_stats()
{
    const int bh = blockIdx.y;
    const int j  = blockIdx.x * 256 + threadIdx.x;
    const float* base = g_SC + (size_t)bh * SEQ * SEQ + j;

    float m = -1e30f, c = 0.f;
    for (int i = 0; i < SEQ; i += 8) {
        float s[8];
#pragma unroll
        for (int u = 0; u < 8; u++) s[u] = base[(size_t)(i + u) * SEQ];
        float mb = s[0];
#pragma unroll
        for (int u = 1; u < 8; u++) mb = fmaxf(mb, s[u]);
        float mn = fmaxf(m, mb);
        float cs = 0.f;
#pragma unroll
        for (int u = 0; u < 8; u++) cs += __expf(s[u] - mn);
        c = c * __expf(m - mn) + cs;
        m = mn;
    }
    g_CM[bh * SEQ + j] = m;
    g_CR[bh * SEQ + j] = 1.0f / c;
}

// ---------------------------------------------------------------------------
// AV GEMM (tf32) with fused softmax normalization on P-tile fill:
//   X[b,i,h,d] = sum_j exp(S[i,j]-m_j)*rcp_j * V[b,j,h,d]
// Block: 128(i) x 64(d), BK=32, 8 warps (4x2), warp 32x32.
// ---------------------------------------------------------------------------
__global__ __launch_bounds__(256) void av_tf32()
{
    __shared__ float Ps[128][36];   // [i][j-chunk] pad 36
    __shared__ float Vs[32][72];    // [j-chunk][d] pad 72 -> banks 8t+g distinct

    const int tid = threadIdx.x;
    const int bh  = blockIdx.y, b = bh >> 4, h = bh & 15;
    const int browi = blockIdx.x * 128;

    const float* Sb = g_SC + (size_t)bh * SEQ * SEQ;
    const float* cm = g_CM + bh * SEQ;
    const float* cr = g_CR + bh * SEQ;
    const float* Vb = g_V + (size_t)b * SEQ * DMODEL + (size_t)h * DHEAD;

    const int w = tid >> 5, lane = tid & 31;
    const int g = lane >> 2, t = lane & 3;
    const int warpM = (w >> 1) * 32, warpN = (w & 1) * 32;

    const int ac4 = (tid & 7) * 4;      // P loader col group (fixed per thread)
    const int vr  = tid >> 4, vc4 = (tid & 15) * 4;

    float acc[2][4][4];
#pragma unroll
    for (int mt = 0; mt < 2; mt++)
#pragma unroll
        for (int nt = 0; nt < 4; nt++)
#pragma unroll
            for (int i = 0; i < 4; i++) acc[mt][nt][i] = 0.f;

    for (int k0 = 0; k0 < SEQ; k0 += 32) {
        // V tile via cp.async
        cp16(&Vs[vr][vc4],      Vb + (size_t)(k0 + vr) * DMODEL + vc4);
        cp16(&Vs[vr + 16][vc4], Vb + (size_t)(k0 + vr + 16) * DMODEL + vc4);
        CP_COMMIT;

        // P tile: load raw scores, normalize, store fp32 to smem
        float m[4], r[4];
#pragma unroll
        for (int u = 0; u < 4; u++) {
            m[u] = cm[k0 + ac4 + u];
            r[u] = cr[k0 + ac4 + u];
        }
#pragma unroll
        for (int i = 0; i < 4; i++) {
            int row = (tid + i * 256) >> 3;
            float4 sv = *(const float4*)(Sb + (size_t)(browi + row) * SEQ + k0 + ac4);
            float4 pv;
            pv.x = __expf(sv.x - m[0]) * r[0];
            pv.y = __expf(sv.y - m[1]) * r[1];
            pv.z = __expf(sv.z - m[2]) * r[2];
            pv.w = __expf(sv.w - m[3]) * r[3];
            *(float4*)&Ps[row][ac4] = pv;
        }
        CP_WAIT0;
        __syncthreads();

#pragma unroll
        for (int ks = 0; ks < 4; ks++) {
            const int k = ks * 8;
            unsigned af[2][4], bf[4][2];
#pragma unroll
            for (int mt = 0; mt < 2; mt++) {
                int rr = warpM + mt * 16 + g;
                af[mt][0] = f2tf(Ps[rr][k + t]);
                af[mt][1] = f2tf(Ps[rr + 8][k + t]);
                af[mt][2] = f2tf(Ps[rr][k + t + 4]);
                af[mt][3] = f2tf(Ps[rr + 8][k + t + 4]);
            }
#pragma unroll
            for (int nt = 0; nt < 4; nt++) {
                int c = warpN + nt * 8 + g;
                bf[nt][0] = f2tf(Vs[k + t][c]);
                bf[nt][1] = f2tf(Vs[k + t + 4][c]);
            }
#pragma unroll
            for (int mt = 0; mt < 2; mt++)
#pragma unroll
                for (int nt = 0; nt < 4; nt++)
                    mma_tf32(acc[mt][nt], af[mt], bf[nt]);
        }
        __syncthreads();
    }

#pragma unroll
    for (int mt = 0; mt < 2; mt++) {
        int r0 = browi + warpM + mt * 16 + g;
        size_t base0 = ((size_t)b * SEQ + r0) * DMODEL + (size_t)h * DHEAD;
#pragma unroll
        for (int nt = 0; nt < 4; nt++) {
            int c = warpN + nt * 8 + 2 * t;
            *(float2*)&g_X[base0 + c] = make_float2(acc[mt][nt][0], acc[mt][nt][1]);
            *(float2*)&g_X[base0 + (size_t)8 * DMODEL + c] = make_float2(acc[mt][nt][2], acc[mt][nt][3]);
        }
    }
}

// ---------------------------------------------------------------------------
// Launch
// ---------------------------------------------------------------------------
extern "C" void kernel_launch(void* const* d_in, const int* in_sizes, int n_in,
                              void* d_out, int out_size)
{
    const float* query = (const float*)d_in[0];
    const float* key_  = (const float*)d_in[1];
    const float* value = (const float*)d_in[2];
    const float* Wq = (const float*)d_in[3];
    const float* bq = (const float*)d_in[4];
    const float* Wk = (const float*)d_in[5];
    const float* bk = (const float*)d_in[6];
    const float* Wv = (const float*)d_in[7];
    const float* bv = (const float*)d_in[8];
    const float* Wo = (const float*)d_in[9];
    const float* bo = (const float*)d_in[10];
    float* out = (float*)d_out;

    float *Qp, *Kp, *Vp, *Xp;
    cudaGetSymbolAddress((void**)&Qp, g_Q);
    cudaGetSymbolAddress((void**)&Kp, g_K);
    cudaGetSymbolAddress((void**)&Vp, g_V);
    cudaGetSymbolAddress((void**)&Xp, g_X);

    dim3 blk(256);
    dim3 gproj(DMODEL / 128, NTOK / 128);   // (8, 32)

    gemm_nn_tf32<<<gproj, blk>>>(query, Wq, bq, Qp, NTOK, DMODEL, DMODEL);
    gemm_nn_tf32<<<gproj, blk>>>(key_,  Wk, bk, Kp, NTOK, DMODEL, DMODEL);
    gemm_nn_tf32<<<gproj, blk>>>(value, Wv, bv, Vp, NTOK, DMODEL, DMODEL);

    qk_tf32<<<dim3(SEQ / 128, SEQ / 128, NBH), blk>>>();
    col_stats<<<dim3(SEQ / 256, NBH), blk>>>();
    av_tf32<<<dim3(SEQ / 128, NBH), blk>>>();

    gemm_nn_tf32<<<gproj, blk>>>(Xp, Wo, bo, out, NTOK, DMODEL, DMODEL);
}

// round 5
// speedup vs baseline: 2.1226x; 1.0007x over previous
#include <cuda_runtime.h>
#include <math.h>

#define BB      2
#define SEQ     2048
#define DMODEL  1024
#define NHEAD   16
#define DHEAD   64
#define NTOK    (BB * SEQ)        // 4096
#define NBH     (BB * NHEAD)      // 32
#define ATTN_SCALE 0.125f         // 1/sqrt(64)

// ---------------------------------------------------------------------------
// Scratch
// ---------------------------------------------------------------------------
__device__ float g_Q [(size_t)NTOK * DMODEL];
__device__ float g_K [(size_t)NTOK * DMODEL];
__device__ float g_V [(size_t)NTOK * DMODEL];
__device__ float g_X [(size_t)NTOK * DMODEL];
__device__ float g_SC[(size_t)NBH * SEQ * SEQ];   // raw scaled scores [bh][i][j]
__device__ float g_CM[NBH * SEQ];                 // per-column max over i
__device__ float g_CR[NBH * SEQ];                 // per-column 1/sum over i

// ---------------------------------------------------------------------------
// Helpers: tf32 convert, mma.m16n8k8, cp.async
// ---------------------------------------------------------------------------
__device__ __forceinline__ unsigned f2tf(float x) {
    unsigned r;
    asm("cvt.rna.tf32.f32 %0, %1;" : "=r"(r) : "f"(x));
    return r;
}

__device__ __forceinline__ void mma_tf32(float* c, const unsigned* a, const unsigned* b) {
    asm volatile(
        "mma.sync.aligned.m16n8k8.row.col.f32.tf32.tf32.f32 "
        "{%0,%1,%2,%3}, {%4,%5,%6,%7}, {%8,%9}, {%0,%1,%2,%3};"
        : "+f"(c[0]), "+f"(c[1]), "+f"(c[2]), "+f"(c[3])
        : "r"(a[0]), "r"(a[1]), "r"(a[2]), "r"(a[3]), "r"(b[0]), "r"(b[1]));
}

__device__ __forceinline__ void cp16(void* smem, const void* g) {
    unsigned s = (unsigned)__cvta_generic_to_shared(smem);
    asm volatile("cp.async.cg.shared.global [%0], [%1], 16;" :: "r"(s), "l"(g));
}
#define CP_COMMIT asm volatile("cp.async.commit_group;")
#define CP_WAIT0  asm volatile("cp.async.wait_group 0;")

// ---------------------------------------------------------------------------
// Projection GEMM (tf32): C[M,N] = A[M,K] @ W[K,N] + bias
// 128x128 block, BK=16 double-buffered cp.async, 8 warps (2x4), warp 64x32.
// ---------------------------------------------------------------------------
__global__ __launch_bounds__(256) void gemm_nn_tf32(
    const float* __restrict__ A, const float* __restrict__ W,
    const float* __restrict__ bias, float* __restrict__ C,
    int M, int N, int K)
{
    __shared__ float As[2][128][20];   // [m][k], pad 20 -> frag banks 20g+t distinct
    __shared__ float Bs[2][16][136];   // [k][n], pad 136 -> frag banks 8t+g distinct

    const int tid  = threadIdx.x;
    const int brow = blockIdx.y * 128;
    const int bcol = blockIdx.x * 128;
    const int w = tid >> 5, lane = tid & 31;
    const int g = lane >> 2, t = lane & 3;
    const int warpM = (w >> 2) * 64;   // 0 / 64
    const int warpN = (w & 3) * 32;    // 0..96

    const int arow = tid >> 2, ac4 = (tid & 3) * 4;
    const int brw  = tid >> 5, bc4 = (tid & 31) * 4;

    float acc[4][4][4];
#pragma unroll
    for (int mt = 0; mt < 4; mt++)
#pragma unroll
        for (int nt = 0; nt < 4; nt++)
#pragma unroll
            for (int i = 0; i < 4; i++) acc[mt][nt][i] = 0.f;

    auto load_tiles = [&](int buf, int k0) {
        cp16(&As[buf][arow][ac4],      A + (size_t)(brow + arow) * K + k0 + ac4);
        cp16(&As[buf][arow + 64][ac4], A + (size_t)(brow + arow + 64) * K + k0 + ac4);
        cp16(&Bs[buf][brw][bc4],       W + (size_t)(k0 + brw) * N + bcol + bc4);
        cp16(&Bs[buf][brw + 8][bc4],   W + (size_t)(k0 + brw + 8) * N + bcol + bc4);
        CP_COMMIT;
    };

    load_tiles(0, 0);
    int buf = 0;
    for (int k0 = 0; k0 < K; k0 += 16) {
        CP_WAIT0;
        __syncthreads();
        if (k0 + 16 < K) load_tiles(buf ^ 1, k0 + 16);
#pragma unroll
        for (int ks = 0; ks < 2; ks++) {
            const int k = ks * 8;
            unsigned af[4][4], bf[4][2];
#pragma unroll
            for (int mt = 0; mt < 4; mt++) {
                int r = warpM + mt * 16 + g;
                af[mt][0] = f2tf(As[buf][r][k + t]);
                af[mt][1] = f2tf(As[buf][r + 8][k + t]);
                af[mt][2] = f2tf(As[buf][r][k + t + 4]);
                af[mt][3] = f2tf(As[buf][r + 8][k + t + 4]);
            }
#pragma unroll
            for (int nt = 0; nt < 4; nt++) {
                int c = warpN + nt * 8 + g;
                bf[nt][0] = f2tf(Bs[buf][k + t][c]);
                bf[nt][1] = f2tf(Bs[buf][k + t + 4][c]);
            }
#pragma unroll
            for (int mt = 0; mt < 4; mt++)
#pragma unroll
                for (int nt = 0; nt < 4; nt++)
                    mma_tf32(acc[mt][nt], af[mt], bf[nt]);
        }
        buf ^= 1;
        __syncthreads();
    }

#pragma unroll
    for (int mt = 0; mt < 4; mt++) {
        int r0 = brow + warpM + mt * 16 + g;
#pragma unroll
        for (int nt = 0; nt < 4; nt++) {
            int c = bcol + warpN + nt * 8 + 2 * t;
            float b0 = bias[c], b1 = bias[c + 1];
            float2 v0 = make_float2(acc[mt][nt][0] + b0, acc[mt][nt][1] + b1);
            float2 v1 = make_float2(acc[mt][nt][2] + b0, acc[mt][nt][3] + b1);
            *(float2*)&C[(size_t)r0 * N + c]       = v0;
            *(float2*)&C[(size_t)(r0 + 8) * N + c] = v1;
        }
    }
}

// ---------------------------------------------------------------------------
// QK^T scores (tf32, NT): S[bh][i][j] = scale * Q[b,i,h,:] . K[b,j,h,:]
// 128x128 block, K=64 in two 32-chunks, 8 warps (2x4).
// ---------------------------------------------------------------------------
__global__ __launch_bounds__(256) void qk_tf32()
{
    __shared__ float Qs[128][36];   // [i][k] pad 36 -> banks 4g+t distinct
    __shared__ float Ks[128][36];   // [j][k] same pattern

    const int tid = threadIdx.x;
    const int bh  = blockIdx.z, b = bh >> 4, h = bh & 15;
    const int browi = blockIdx.y * 128;
    const int bcolj = blockIdx.x * 128;

    const float* Qb = g_Q + (size_t)b * SEQ * DMODEL + (size_t)h * DHEAD;
    const float* Kb = g_K + (size_t)b * SEQ * DMODEL + (size_t)h * DHEAD;
    float*       Cb = g_SC + (size_t)bh * SEQ * SEQ;

    const int w = tid >> 5, lane = tid & 31;
    const int g = lane >> 2, t = lane & 3;
    const int warpM = (w >> 2) * 64, warpN = (w & 3) * 32;
    const int lc4 = (tid & 7) * 4;

    float acc[4][4][4];
#pragma unroll
    for (int mt = 0; mt < 4; mt++)
#pragma unroll
        for (int nt = 0; nt < 4; nt++)
#pragma unroll
            for (int i = 0; i < 4; i++) acc[mt][nt][i] = 0.f;

    for (int k0 = 0; k0 < DHEAD; k0 += 32) {
#pragma unroll
        for (int i = 0; i < 4; i++) {
            int row = (tid + i * 256) >> 3;
            cp16(&Qs[row][lc4], Qb + (size_t)(browi + row) * DMODEL + k0 + lc4);
            cp16(&Ks[row][lc4], Kb + (size_t)(bcolj + row) * DMODEL + k0 + lc4);
        }
        CP_COMMIT; CP_WAIT0;
        __syncthreads();
#pragma unroll
        for (int ks = 0; ks < 4; ks++) {
            const int k = ks * 8;
            unsigned af[4][4], bf[4][2];
#pragma unroll
            for (int mt = 0; mt < 4; mt++) {
                int r = warpM + mt * 16 + g;
                af[mt][0] = f2tf(Qs[r][k + t]);
                af[mt][1] = f2tf(Qs[r + 8][k + t]);
                af[mt][2] = f2tf(Qs[r][k + t + 4]);
                af[mt][3] = f2tf(Qs[r + 8][k + t + 4]);
            }
#pragma unroll
            for (int nt = 0; nt < 4; nt++) {
                int c = warpN + nt * 8 + g;
                bf[nt][0] = f2tf(Ks[c][k + t]);
                bf[nt][1] = f2tf(Ks[c][k + t + 4]);
            }
#pragma unroll
            for (int mt = 0; mt < 4; mt++)
#pragma unroll
                for (int nt = 0; nt < 4; nt++)
                    mma_tf32(acc[mt][nt], af[mt], bf[nt]);
        }
        __syncthreads();
    }

#pragma unroll
    for (int mt = 0; mt < 4; mt++) {
        int r0 = browi + warpM + mt * 16 + g;
#pragma unroll
        for (int nt = 0; nt < 4; nt++) {
            int c = bcolj + warpN + nt * 8 + 2 * t;
            float2 v0 = make_float2(acc[mt][nt][0] * ATTN_SCALE, acc[mt][nt][1] * ATTN_SCALE);
            float2 v1 = make_float2(acc[mt][nt][2] * ATTN_SCALE, acc[mt][nt][3] * ATTN_SCALE);
            *(float2*)&Cb[(size_t)r0 * SEQ + c]       = v0;
            *(float2*)&Cb[(size_t)(r0 + 8) * SEQ + c] = v1;
        }
    }
}

// ---------------------------------------------------------------------------
// Column stats over i (softmax axis=1): per (bh, j): max and 1/sum. fp32.
// ---------------------------------------------------------------------------
__global__ __launch_bounds__(256) void col_stats()
{
    const int bh = blockIdx.y;
    const int j  = blockIdx.x * 256 + threadIdx.x;
    const float* base = g_SC + (size_t)bh * SEQ * SEQ + j;

    float m = -1e30f, c = 0.f;
    for (int i = 0; i < SEQ; i += 8) {
        float s[8];
#pragma unroll
        for (int u = 0; u < 8; u++) s[u] = base[(size_t)(i + u) * SEQ];
        float mb = s[0];
#pragma unroll
        for (int u = 1; u < 8; u++) mb = fmaxf(mb, s[u]);
        float mn = fmaxf(m, mb);
        float cs = 0.f;
#pragma unroll
        for (int u = 0; u < 8; u++) cs += __expf(s[u] - mn);
        c = c * __expf(m - mn) + cs;
        m = mn;
    }
    g_CM[bh * SEQ + j] = m;
    g_CR[bh * SEQ + j] = 1.0f / c;
}

// ---------------------------------------------------------------------------
// AV GEMM (tf32) with fused softmax normalization on P-tile fill:
//   X[b,i,h,d] = sum_j exp(S[i,j]-m_j)*rcp_j * V[b,j,h,d]
// Block: 128(i) x 64(d), BK=32, 8 warps (4x2), warp 32x32.
// ---------------------------------------------------------------------------
__global__ __launch_bounds__(256) void av_tf32()
{
    __shared__ float Ps[128][36];   // [i][j-chunk] pad 36
    __shared__ float Vs[32][72];    // [j-chunk][d] pad 72 -> banks 8t+g distinct

    const int tid = threadIdx.x;
    const int bh  = blockIdx.y, b = bh >> 4, h = bh & 15;
    const int browi = blockIdx.x * 128;

    const float* Sb = g_SC + (size_t)bh * SEQ * SEQ;
    const float* cm = g_CM + bh * SEQ;
    const float* cr = g_CR + bh * SEQ;
    const float* Vb = g_V + (size_t)b * SEQ * DMODEL + (size_t)h * DHEAD;

    const int w = tid >> 5, lane = tid & 31;
    const int g = lane >> 2, t = lane & 3;
    const int warpM = (w >> 1) * 32, warpN = (w & 1) * 32;

    const int ac4 = (tid & 7) * 4;      // P loader col group (fixed per thread)
    const int vr  = tid >> 4, vc4 = (tid & 15) * 4;

    float acc[2][4][4];
#pragma unroll
    for (int mt = 0; mt < 2; mt++)
#pragma unroll
        for (int nt = 0; nt < 4; nt++)
#pragma unroll
            for (int i = 0; i < 4; i++) acc[mt][nt][i] = 0.f;

    for (int k0 = 0; k0 < SEQ; k0 += 32) {
        // V tile via cp.async
        cp16(&Vs[vr][vc4],      Vb + (size_t)(k0 + vr) * DMODEL + vc4);
        cp16(&Vs[vr + 16][vc4], Vb + (size_t)(k0 + vr + 16) * DMODEL + vc4);
        CP_COMMIT;

        // P tile: load raw scores, normalize, store fp32 to smem
        float m[4], r[4];
#pragma unroll
        for (int u = 0; u < 4; u++) {
            m[u] = cm[k0 + ac4 + u];
            r[u] = cr[k0 + ac4 + u];
        }
#pragma unroll
        for (int i = 0; i < 4; i++) {
            int row = (tid + i * 256) >> 3;
            float4 sv = *(const float4*)(Sb + (size_t)(browi + row) * SEQ + k0 + ac4);
            float4 pv;
            pv.x = __expf(sv.x - m[0]) * r[0];
            pv.y = __expf(sv.y - m[1]) * r[1];
            pv.z = __expf(sv.z - m[2]) * r[2];
            pv.w = __expf(sv.w - m[3]) * r[3];
            *(float4*)&Ps[row][ac4] = pv;
        }
        CP_WAIT0;
        __syncthreads();

#pragma unroll
        for (int ks = 0; ks < 4; ks++) {
            const int k = ks * 8;
            unsigned af[2][4], bf[4][2];
#pragma unroll
            for (int mt = 0; mt < 2; mt++) {
                int rr = warpM + mt * 16 + g;
                af[mt][0] = f2tf(Ps[rr][k + t]);
                af[mt][1] = f2tf(Ps[rr + 8][k + t]);
                af[mt][2] = f2tf(Ps[rr][k + t + 4]);
                af[mt][3] = f2tf(Ps[rr + 8][k + t + 4]);
            }
#pragma unroll
            for (int nt = 0; nt < 4; nt++) {
                int c = warpN + nt * 8 + g;
                bf[nt][0] = f2tf(Vs[k + t][c]);
                bf[nt][1] = f2tf(Vs[k + t + 4][c]);
            }
#pragma unroll
            for (int mt = 0; mt < 2; mt++)
#pragma unroll
                for (int nt = 0; nt < 4; nt++)
                    mma_tf32(acc[mt][nt], af[mt], bf[nt]);
        }
        __syncthreads();
    }

#pragma unroll
    for (int mt = 0; mt < 2; mt++) {
        int r0 = browi + warpM + mt * 16 + g;
        size_t base0 = ((size_t)b * SEQ + r0) * DMODEL + (size_t)h * DHEAD;
#pragma unroll
        for (int nt = 0; nt < 4; nt++) {
            int c = warpN + nt * 8 + 2 * t;
            *(float2*)&g_X[base0 + c] = make_float2(acc[mt][nt][0], acc[mt][nt][1]);
            *(float2*)&g_X[base0 + (size_t)8 * DMODEL + c] = make_float2(acc[mt][nt][2], acc[mt][nt][3]);
        }
    }
}

// ---------------------------------------------------------------------------
// Launch
// ---------------------------------------------------------------------------
extern "C" void kernel_launch(void* const* d_in, const int* in_sizes, int n_in,
                              void* d_out, int out_size)
{
    const float* query = (const float*)d_in[0];
    const float* key_  = (const float*)d_in[1];
    const float* value = (const float*)d_in[2];
    const float* Wq = (const float*)d_in[3];
    const float* bq = (const float*)d_in[4];
    const float* Wk = (const float*)d_in[5];
    const float* bk = (const float*)d_in[6];
    const float* Wv = (const float*)d_in[7];
    const float* bv = (const float*)d_in[8];
    const float* Wo = (const float*)d_in[9];
    const float* bo = (const float*)d_in[10];
    float* out = (float*)d_out;

    float *Qp, *Kp, *Vp, *Xp;
    cudaGetSymbolAddress((void**)&Qp, g_Q);
    cudaGetSymbolAddress((void**)&Kp, g_K);
    cudaGetSymbolAddress((void**)&Vp, g_V);
    cudaGetSymbolAddress((void**)&Xp, g_X);

    dim3 blk(256);
    dim3 gproj(DMODEL / 128, NTOK / 128);   // (8, 32)

    gemm_nn_tf32<<<gproj, blk>>>(query, Wq, bq, Qp, NTOK, DMODEL, DMODEL);
    gemm_nn_tf32<<<gproj, blk>>>(key_,  Wk, bk, Kp, NTOK, DMODEL, DMODEL);
    gemm_nn_tf32<<<gproj, blk>>>(value, Wv, bv, Vp, NTOK, DMODEL, DMODEL);

    qk_tf32<<<dim3(SEQ / 128, SEQ / 128, NBH), blk>>>();
    col_stats<<<dim3(SEQ / 256, NBH), blk>>>();
    av_tf32<<<dim3(SEQ / 128, NBH), blk>>>();

    gemm_nn_tf32<<<gproj, blk>>>(Xp, Wo, bo, out, NTOK, DMODEL, DMODEL);
}

// round 6
// speedup vs baseline: 2.6637x; 1.2550x over previous
#include <cuda_runtime.h>
#include <math.h>

#define BB      2
#define SEQ     2048
#define DMODEL  1024
#define NHEAD   16
#define DHEAD   64
#define NTOK    (BB * SEQ)        // 4096
#define NBH     (BB * NHEAD)      // 32
#define ATTN_SCALE 0.125f         // 1/sqrt(64)

// ---------------------------------------------------------------------------
// Scratch
// ---------------------------------------------------------------------------
__device__ float g_Q [(size_t)NTOK * DMODEL];
__device__ float g_K [(size_t)NTOK * DMODEL];
__device__ float g_V [(size_t)NTOK * DMODEL];
__device__ float g_X [(size_t)NTOK * DMODEL];
__device__ float g_SC[(size_t)NBH * SEQ * SEQ];   // raw scaled scores [bh][i][j]
__device__ float g_CM[NBH * SEQ];                 // per-column max over i
__device__ float g_CR[NBH * SEQ];                 // per-column 1/sum over i

// ---------------------------------------------------------------------------
// Helpers
// ---------------------------------------------------------------------------
__device__ __forceinline__ float tfbits(float x) {   // tf32-round, keep as float bits
    unsigned r;
    asm("cvt.rna.tf32.f32 %0, %1;" : "=r"(r) : "f"(x));
    return __uint_as_float(r);
}
__device__ __forceinline__ float4 tf4(float4 v) {
    return make_float4(tfbits(v.x), tfbits(v.y), tfbits(v.z), tfbits(v.w));
}
__device__ __forceinline__ unsigned ub(float x) { return __float_as_uint(x); }

__device__ __forceinline__ void mma_tf32(float* c, const unsigned* a, const unsigned* b) {
    asm volatile(
        "mma.sync.aligned.m16n8k8.row.col.f32.tf32.tf32.f32 "
        "{%0,%1,%2,%3}, {%4,%5,%6,%7}, {%8,%9}, {%0,%1,%2,%3};"
        : "+f"(c[0]), "+f"(c[1]), "+f"(c[2]), "+f"(c[3])
        : "r"(a[0]), "r"(a[1]), "r"(a[2]), "r"(a[3]), "r"(b[0]), "r"(b[1]));
}

// ---------------------------------------------------------------------------
// Projection GEMM (tf32, pre-converted smem): C[M,1024] = A[M,1024] @ W + bias
// 128x128 block, BK=32, register-staged LDG->cvt->STS, pure LDS+MMA mainloop.
// gridDim.z selects (A,W,bias,C) set -> one launch covers Q,K,V projections.
// ---------------------------------------------------------------------------
__global__ __launch_bounds__(256, 2) void proj_tf32(
    const float* __restrict__ A0, const float* __restrict__ A1, const float* __restrict__ A2,
    const float* __restrict__ W0, const float* __restrict__ W1, const float* __restrict__ W2,
    const float* __restrict__ b0_, const float* __restrict__ b1_, const float* __restrict__ b2_,
    float* __restrict__ C0, float* __restrict__ C1, float* __restrict__ C2)
{
    constexpr int N = DMODEL, K = DMODEL;
    __shared__ float As[128][36];    // [m][k] tf32 bits; frag bank = 4g+t (distinct)
    __shared__ float Bs[32][136];    // [k][n] tf32 bits; frag bank = 8t+g (distinct)

    const int z = blockIdx.z;
    const float* A    = z == 0 ? A0  : (z == 1 ? A1  : A2);
    const float* W    = z == 0 ? W0  : (z == 1 ? W1  : W2);
    const float* bias = z == 0 ? b0_ : (z == 1 ? b1_ : b2_);
    float*       C    = z == 0 ? C0  : (z == 1 ? C1  : C2);

    const int tid  = threadIdx.x;
    const int brow = blockIdx.y * 128;
    const int bcol = blockIdx.x * 128;
    const int w = tid >> 5, lane = tid & 31;
    const int g = lane >> 2, t = lane & 3;
    const int warpM = (w >> 2) * 64, warpN = (w & 3) * 32;

    const int ar = tid >> 3, ac4 = (tid & 7) * 4;    // A: rows ar+i*32, k-cols ac4
    const int br = tid >> 5, bc4 = (tid & 31) * 4;   // B: rows br+i*8,  n-cols bc4

    const float* Ap = A + (size_t)(brow + ar) * K + ac4;
    const float* Wp = W + (size_t)br * N + bcol + bc4;

    float4 ra[4], rb[4];
#pragma unroll
    for (int i = 0; i < 4; i++) ra[i] = *(const float4*)(Ap + (size_t)i * 32 * K);
#pragma unroll
    for (int i = 0; i < 4; i++) rb[i] = *(const float4*)(Wp + (size_t)i * 8 * N);

    float acc[4][4][4];
#pragma unroll
    for (int mt = 0; mt < 4; mt++)
#pragma unroll
        for (int nt = 0; nt < 4; nt++)
#pragma unroll
            for (int i = 0; i < 4; i++) acc[mt][nt][i] = 0.f;

    for (int k0 = 0; k0 < K; k0 += 32) {
#pragma unroll
        for (int i = 0; i < 4; i++) *(float4*)&As[ar + i * 32][ac4] = tf4(ra[i]);
#pragma unroll
        for (int i = 0; i < 4; i++) *(float4*)&Bs[br + i * 8][bc4]  = tf4(rb[i]);
        __syncthreads();

        if (k0 + 32 < K) {
#pragma unroll
            for (int i = 0; i < 4; i++)
                ra[i] = *(const float4*)(Ap + k0 + 32 + (size_t)i * 32 * K);
#pragma unroll
            for (int i = 0; i < 4; i++)
                rb[i] = *(const float4*)(Wp + (size_t)(k0 + 32 + i * 8) * N);
        }

#pragma unroll
        for (int ks = 0; ks < 4; ks++) {
            const int k = ks * 8;
            unsigned bfr[4][2];
#pragma unroll
            for (int nt = 0; nt < 4; nt++) {
                int c = warpN + nt * 8 + g;
                bfr[nt][0] = ub(Bs[k + t][c]);
                bfr[nt][1] = ub(Bs[k + t + 4][c]);
            }
#pragma unroll
            for (int mt = 0; mt < 4; mt++) {
                int r = warpM + mt * 16 + g;
                unsigned af[4] = { ub(As[r][k + t]),     ub(As[r + 8][k + t]),
                                   ub(As[r][k + t + 4]), ub(As[r + 8][k + t + 4]) };
#pragma unroll
                for (int nt = 0; nt < 4; nt++) mma_tf32(acc[mt][nt], af, bfr[nt]);
            }
        }
        __syncthreads();
    }

#pragma unroll
    for (int mt = 0; mt < 4; mt++) {
        int r0 = brow + warpM + mt * 16 + g;
#pragma unroll
        for (int nt = 0; nt < 4; nt++) {
            int c = bcol + warpN + nt * 8 + 2 * t;
            float bb0 = bias[c], bb1 = bias[c + 1];
            *(float2*)&C[(size_t)r0 * N + c]       = make_float2(acc[mt][nt][0] + bb0, acc[mt][nt][1] + bb1);
            *(float2*)&C[(size_t)(r0 + 8) * N + c] = make_float2(acc[mt][nt][2] + bb0, acc[mt][nt][3] + bb1);
        }
    }
}

// ---------------------------------------------------------------------------
// QK^T scores (tf32 NT, pre-converted smem): S = scale * Q . K^T
// 128x128 block, K=64 in two 32-chunks.
// ---------------------------------------------------------------------------
__global__ __launch_bounds__(256, 2) void qk_tf32()
{
    __shared__ float Qs[128][36];   // [i][k]
    __shared__ float Ks[128][36];   // [j][k]

    const int tid = threadIdx.x;
    const int bh  = blockIdx.z, b = bh >> 4, h = bh & 15;
    const int browi = blockIdx.y * 128;
    const int bcolj = blockIdx.x * 128;

    const float* Qb = g_Q + (size_t)b * SEQ * DMODEL + (size_t)h * DHEAD;
    const float* Kb = g_K + (size_t)b * SEQ * DMODEL + (size_t)h * DHEAD;
    float*       Cb = g_SC + (size_t)bh * SEQ * SEQ;

    const int w = tid >> 5, lane = tid & 31;
    const int g = lane >> 2, t = lane & 3;
    const int warpM = (w >> 2) * 64, warpN = (w & 3) * 32;

    const int lr = tid >> 3, lc4 = (tid & 7) * 4;
    const float* Qp = Qb + (size_t)(browi + lr) * DMODEL + lc4;
    const float* Kp = Kb + (size_t)(bcolj + lr) * DMODEL + lc4;

    float4 rq[4], rk[4];
#pragma unroll
    for (int i = 0; i < 4; i++) {
        rq[i] = *(const float4*)(Qp + (size_t)i * 32 * DMODEL);
        rk[i] = *(const float4*)(Kp + (size_t)i * 32 * DMODEL);
    }

    float acc[4][4][4];
#pragma unroll
    for (int mt = 0; mt < 4; mt++)
#pragma unroll
        for (int nt = 0; nt < 4; nt++)
#pragma unroll
            for (int i = 0; i < 4; i++) acc[mt][nt][i] = 0.f;

    for (int k0 = 0; k0 < DHEAD; k0 += 32) {
#pragma unroll
        for (int i = 0; i < 4; i++) {
            *(float4*)&Qs[lr + i * 32][lc4] = tf4(rq[i]);
            *(float4*)&Ks[lr + i * 32][lc4] = tf4(rk[i]);
        }
        __syncthreads();

        if (k0 == 0) {
#pragma unroll
            for (int i = 0; i < 4; i++) {
                rq[i] = *(const float4*)(Qp + 32 + (size_t)i * 32 * DMODEL);
                rk[i] = *(const float4*)(Kp + 32 + (size_t)i * 32 * DMODEL);
            }
        }

#pragma unroll
        for (int ks = 0; ks < 4; ks++) {
            const int k = ks * 8;
            unsigned bfr[4][2];
#pragma unroll
            for (int nt = 0; nt < 4; nt++) {
                int c = warpN + nt * 8 + g;
                bfr[nt][0] = ub(Ks[c][k + t]);
                bfr[nt][1] = ub(Ks[c][k + t + 4]);
            }
#pragma unroll
            for (int mt = 0; mt < 4; mt++) {
                int r = warpM + mt * 16 + g;
                unsigned af[4] = { ub(Qs[r][k + t]),     ub(Qs[r + 8][k + t]),
                                   ub(Qs[r][k + t + 4]), ub(Qs[r + 8][k + t + 4]) };
#pragma unroll
                for (int nt = 0; nt < 4; nt++) mma_tf32(acc[mt][nt], af, bfr[nt]);
            }
        }
        __syncthreads();
    }

#pragma unroll
    for (int mt = 0; mt < 4; mt++) {
        int r0 = browi + warpM + mt * 16 + g;
#pragma unroll
        for (int nt = 0; nt < 4; nt++) {
            int c = bcolj + warpN + nt * 8 + 2 * t;
            *(float2*)&Cb[(size_t)r0 * SEQ + c] =
                make_float2(acc[mt][nt][0] * ATTN_SCALE, acc[mt][nt][1] * ATTN_SCALE);
            *(float2*)&Cb[(size_t)(r0 + 8) * SEQ + c] =
                make_float2(acc[mt][nt][2] * ATTN_SCALE, acc[mt][nt][3] * ATTN_SCALE);
        }
    }
}

// ---------------------------------------------------------------------------
// Column stats over i (softmax axis=1): per (bh, j): max and 1/sum. fp32.
// ---------------------------------------------------------------------------
__global__ __launch_bounds__(256) void col_stats()
{
    const int bh = blockIdx.y;
    const int j  = blockIdx.x * 256 + threadIdx.x;
    const float* base = g_SC + (size_t)bh * SEQ * SEQ + j;

    float m = -1e30f, c = 0.f;
    for (int i = 0; i < SEQ; i += 8) {
        float s[8];
#pragma unroll
        for (int u = 0; u < 8; u++) s[u] = base[(size_t)(i + u) * SEQ];
        float mb = s[0];
#pragma unroll
        for (int u = 1; u < 8; u++) mb = fmaxf(mb, s[u]);
        float mn = fmaxf(m, mb);
        float cs = 0.f;
#pragma unroll
        for (int u = 0; u < 8; u++) cs += __expf(s[u] - mn);
        c = c * __expf(m - mn) + cs;
        m = mn;
    }
    g_CM[bh * SEQ + j] = m;
    g_CR[bh * SEQ + j] = 1.0f / c;
}

// ---------------------------------------------------------------------------
// AV GEMM (tf32, pre-converted smem) with fused softmax on P fill:
//   X[b,i,h,d] = sum_j exp(S[i,j]-m_j)*rcp_j * V[b,j,h,d]
// 128(i) x 64(d) block, BK=32 over j, register-staged pipeline.
// ---------------------------------------------------------------------------
__global__ __launch_bounds__(256, 2) void av_tf32()
{
    __shared__ float Ps[128][36];   // [i][j-local]
    __shared__ float Vs[32][72];    // [j-local][d]

    const int tid = threadIdx.x;
    const int bh  = blockIdx.y, b = bh >> 4, h = bh & 15;
    const int browi = blockIdx.x * 128;

    const float* Sb = g_SC + (size_t)bh * SEQ * SEQ;
    const float* cm = g_CM + bh * SEQ;
    const float* cr = g_CR + bh * SEQ;
    const float* Vb = g_V + (size_t)b * SEQ * DMODEL + (size_t)h * DHEAD;

    const int w = tid >> 5, lane = tid & 31;
    const int g = lane >> 2, t = lane & 3;
    const int warpM = (w >> 1) * 32, warpN = (w & 1) * 32;

    const int pr = tid >> 3, pc4 = (tid & 7) * 4;    // P: rows pr+i*32, col jc
    const int vr = tid >> 4, vc4 = (tid & 15) * 4;   // V: rows vr+i*16

    float4 rs[4], rv[2], rm, rr;
#pragma unroll
    for (int i = 0; i < 4; i++)
        rs[i] = *(const float4*)(Sb + (size_t)(browi + pr + i * 32) * SEQ + pc4);
#pragma unroll
    for (int i = 0; i < 2; i++)
        rv[i] = *(const float4*)(Vb + (size_t)(vr + i * 16) * DMODEL + vc4);
    rm = *(const float4*)&cm[pc4];
    rr = *(const float4*)&cr[pc4];

    float acc[2][4][4];
#pragma unroll
    for (int mt = 0; mt < 2; mt++)
#pragma unroll
        for (int nt = 0; nt < 4; nt++)
#pragma unroll
            for (int i = 0; i < 4; i++) acc[mt][nt][i] = 0.f;

    for (int k0 = 0; k0 < SEQ; k0 += 32) {
        // P fill: exp-normalize + tf32 cvt
#pragma unroll
        for (int i = 0; i < 4; i++) {
            float4 s = rs[i];
            *(float4*)&Ps[pr + i * 32][pc4] = make_float4(
                tfbits(__expf(s.x - rm.x) * rr.x),
                tfbits(__expf(s.y - rm.y) * rr.y),
                tfbits(__expf(s.z - rm.z) * rr.z),
                tfbits(__expf(s.w - rm.w) * rr.w));
        }
#pragma unroll
        for (int i = 0; i < 2; i++) *(float4*)&Vs[vr + i * 16][vc4] = tf4(rv[i]);
        __syncthreads();

        if (k0 + 32 < SEQ) {
            const int kn = k0 + 32;
#pragma unroll
            for (int i = 0; i < 4; i++)
                rs[i] = *(const float4*)(Sb + (size_t)(browi + pr + i * 32) * SEQ + kn + pc4);
#pragma unroll
            for (int i = 0; i < 2; i++)
                rv[i] = *(const float4*)(Vb + (size_t)(kn + vr + i * 16) * DMODEL + vc4);
            rm = *(const float4*)&cm[kn + pc4];
            rr = *(const float4*)&cr[kn + pc4];
        }

#pragma unroll
        for (int ks = 0; ks < 4; ks++) {
            const int k = ks * 8;
            unsigned bfr[4][2];
#pragma unroll
            for (int nt = 0; nt < 4; nt++) {
                int c = warpN + nt * 8 + g;
                bfr[nt][0] = ub(Vs[k + t][c]);
                bfr[nt][1] = ub(Vs[k + t + 4][c]);
            }
#pragma unroll
            for (int mt = 0; mt < 2; mt++) {
                int r = warpM + mt * 16 + g;
                unsigned af[4] = { ub(Ps[r][k + t]),     ub(Ps[r + 8][k + t]),
                                   ub(Ps[r][k + t + 4]), ub(Ps[r + 8][k + t + 4]) };
#pragma unroll
                for (int nt = 0; nt < 4; nt++) mma_tf32(acc[mt][nt], af, bfr[nt]);
            }
        }
        __syncthreads();
    }

#pragma unroll
    for (int mt = 0; mt < 2; mt++) {
        int r0 = browi + warpM + mt * 16 + g;
        size_t base0 = ((size_t)b * SEQ + r0) * DMODEL + (size_t)h * DHEAD;
#pragma unroll
        for (int nt = 0; nt < 4; nt++) {
            int c = warpN + nt * 8 + 2 * t;
            *(float2*)&g_X[base0 + c] = make_float2(acc[mt][nt][0], acc[mt][nt][1]);
            *(float2*)&g_X[base0 + (size_t)8 * DMODEL + c] = make_float2(acc[mt][nt][2], acc[mt][nt][3]);
        }
    }
}

// ---------------------------------------------------------------------------
// Launch
// ---------------------------------------------------------------------------
extern "C" void kernel_launch(void* const* d_in, const int* in_sizes, int n_in,
                              void* d_out, int out_size)
{
    const float* query = (const float*)d_in[0];
    const float* key_  = (const float*)d_in[1];
    const float* value = (const float*)d_in[2];
    const float* Wq = (const float*)d_in[3];
    const float* bq = (const float*)d_in[4];
    const float* Wk = (const float*)d_in[5];
    const float* bk = (const float*)d_in[6];
    const float* Wv = (const float*)d_in[7];
    const float* bv = (const float*)d_in[8];
    const float* Wo = (const float*)d_in[9];
    const float* bo = (const float*)d_in[10];
    float* out = (float*)d_out;

    float *Qp, *Kp, *Vp, *Xp;
    cudaGetSymbolAddress((void**)&Qp, g_Q);
    cudaGetSymbolAddress((void**)&Kp, g_K);
    cudaGetSymbolAddress((void**)&Vp, g_V);
    cudaGetSymbolAddress((void**)&Xp, g_X);

    dim3 blk(256);

    // Fused Q/K/V projections: one launch, z selects the set
    proj_tf32<<<dim3(DMODEL / 128, NTOK / 128, 3), blk>>>(
        query, key_, value, Wq, Wk, Wv, bq, bk, bv, Qp, Kp, Vp);

    qk_tf32<<<dim3(SEQ / 128, SEQ / 128, NBH), blk>>>();
    col_stats<<<dim3(SEQ / 256, NBH), blk>>>();
    av_tf32<<<dim3(SEQ / 128, NBH), blk>>>();

    // Output projection (same kernel, z=0 path)
    proj_tf32<<<dim3(DMODEL / 128, NTOK / 128, 1), blk>>>(
        Xp, Xp, Xp, Wo, Wo, Wo, bo, bo, bo, out, out, out);
}